// round 4
// baseline (speedup 1.0000x reference)
#include <cuda_runtime.h>
#include <cstdint>

// Problem constants
#define NB   256
#define SEQ  720
#define PRED 720
#define RNK  16
#define CTXD 128
#define HIDD 64
#define ODIM (RNK*(SEQ+PRED))   // 23040
#define BOFF (RNK*PRED)         // 11520, B_delta at h[b][11520 + r*720 + s]
#define YSZ  (NB*PRED)          // 184320

// Scratch (device globals: allocation-free)
__device__ __align__(128) float g_hidden[NB*HIDD];
__device__ __align__(128) float g_h[(size_t)NB*ODIM];   // hyper-MLP output, 23.6 MB

// ---------------- packed f32x2 + async-copy helpers ----------------
__device__ __forceinline__ unsigned long long ffma2(unsigned long long a,
                                                    unsigned long long b,
                                                    unsigned long long c) {
    unsigned long long d;
    asm("fma.rn.f32x2 %0, %1, %2, %3;" : "=l"(d) : "l"(a), "l"(b), "l"(c));
    return d;
}
__device__ __forceinline__ unsigned long long dup2(float a) {
    unsigned long long d;
    asm("mov.b64 %0, {%1, %1};" : "=l"(d) : "f"(a));
    return d;
}
__device__ __forceinline__ float4 u2f4(unsigned long long a, unsigned long long b) {
    union { ulonglong2 u; float4 f; } c; c.u.x = a; c.u.y = b; return c.f;
}
__device__ __forceinline__ void unpack2(unsigned long long v, float& lo, float& hi) {
    asm("mov.b64 {%0, %1}, %2;" : "=f"(lo), "=f"(hi) : "l"(v));
}
__device__ __forceinline__ void cp16(void* smem_dst, const void* gmem_src) {
    unsigned s = (unsigned)__cvta_generic_to_shared(smem_dst);
    asm volatile("cp.async.cg.shared.global [%0], [%1], 16;" :: "r"(s), "l"(gmem_src));
}
#define CP_COMMIT() asm volatile("cp.async.commit_group;")
#define CP_WAIT0()  asm volatile("cp.async.wait_group 0;")

// ---------------- kernel 1a: hidden = relu(ctx @ W1^T + b1) ----------------
__global__ void hidden_kernel(const float* __restrict__ ctx,
                              const float* __restrict__ W1,
                              const float* __restrict__ b1) {
    __shared__ float sc[CTXD];
    int b = blockIdx.x;
    int t = threadIdx.x;               // 128 threads
    sc[t] = ctx[b*CTXD + t];
    __syncthreads();
    if (t < HIDD) {
        float s = b1[t];
        const float* w = W1 + t*CTXD;
        #pragma unroll 16
        for (int k = 0; k < CTXD; ++k) s += w[k]*sc[k];
        g_hidden[b*HIDD + t] = fmaxf(s, 0.f);
    }
}

// ---------------- kernel 1b: h = hidden @ W2^T + b2  (M=23040,N=256,K=64) ----
__global__ void __launch_bounds__(256) mlp2_kernel(const float* __restrict__ W2,
                                                   const float* __restrict__ b2) {
    __shared__ float sW2T[64*68];   // [k][o_local]
    __shared__ float sHT [64*68];   // [k][b_local]
    const int tx = threadIdx.x, ty = threadIdx.y;
    const int tid = ty*16 + tx;
    const int o0 = blockIdx.x*64, b0 = blockIdx.y*64;

    for (int idx = tid; idx < 4096; idx += 256) {
        int i = idx >> 6, k = idx & 63;
        sW2T[k*68 + i] = W2[(size_t)(o0+i)*HIDD + k];
        sHT [k*68 + i] = g_hidden[(b0+i)*HIDD + k];
    }
    __syncthreads();

    unsigned long long acc[4][2];
    #pragma unroll
    for (int j = 0; j < 4; ++j) { acc[j][0] = 0ull; acc[j][1] = 0ull; }

    #pragma unroll 16
    for (int k = 0; k < 64; ++k) {
        float4 hb = *reinterpret_cast<const float4*>(&sHT[k*68 + tx*4]);
        ulonglong2 w = *reinterpret_cast<const ulonglong2*>(&sW2T[k*68 + ty*4]);
        const float hv[4] = {hb.x, hb.y, hb.z, hb.w};
        #pragma unroll
        for (int j = 0; j < 4; ++j) {
            unsigned long long ap = dup2(hv[j]);
            acc[j][0] = ffma2(ap, w.x, acc[j][0]);
            acc[j][1] = ffma2(ap, w.y, acc[j][1]);
        }
    }
    float4 bias = *reinterpret_cast<const float4*>(&b2[o0 + ty*4]);
    #pragma unroll
    for (int j = 0; j < 4; ++j) {
        float4 v = u2f4(acc[j][0], acc[j][1]);
        v.x += bias.x; v.y += bias.y; v.z += bias.z; v.w += bias.w;
        *reinterpret_cast<float4*>(&g_h[(size_t)(b0 + tx*4 + j)*ODIM + o0 + ty*4]) = v;
    }
}

// ---------------- kernel 2: zero y ----------------
__global__ void zy_kernel(float* __restrict__ y) {
    int i = blockIdx.x*256 + threadIdx.x;     // grid 180, YSZ/4 = 46080 float4
    reinterpret_cast<float4*>(y)[i] = make_float4(0.f, 0.f, 0.f, 0.f);
}

// ---------------- kernel 3: W_eff = W + A@B, fused y = W_eff @ x ------------
// Tile TP=48 x TS=240, thread tile 8p x 8s, 192 threads (180 active compute).
// Double-buffered cp.async (B tile + x slice) + reg-prefetched A.
// y accumulated via atomicAdd (RED.ADD.F32), zero-initialized by zy_kernel.
#define TP 48
#define TS 240
#define SB_F (16*TS)                       // 3840 floats per B buffer
#define SA_F (TP*RNK)                      // 768 pairs per A buffer
// smem: sW 11520f + sB 2*3840f + sx 2*240f + sA 2*768 float2
#define WEFF_SMEM ((TP*TS + 2*SB_F + 2*TS)*4 + 2*SA_F*8)   // 91008 bytes

__global__ void __launch_bounds__(192, 2) weff_kernel(const float* __restrict__ W,
                                                      const float* __restrict__ xg,
                                                      float* __restrict__ weff,
                                                      float* __restrict__ yout) {
    extern __shared__ float smem[];
    float*  sW = smem;                                    // [TP][TS]
    float*  sB = smem + TP*TS;                            // [2][16][TS]
    float*  sx = smem + TP*TS + 2*SB_F;                   // [2][TS]
    float2* sA = reinterpret_cast<float2*>(smem + TP*TS + 2*SB_F + 2*TS); // [2][768]

    const int tid = threadIdx.x;                          // 192 threads
    const int p0 = blockIdx.x * TP;
    const int s0 = blockIdx.y * TS;
    const int b_beg = blockIdx.z * 43;
    const int b_end = min(NB, b_beg + 43);
    const bool active = (tid < 180);
    const int pg = tid / 30;            // 0..5, 8 p-rows each
    const int sg = tid % 30;            // 8 s (4 f32x2 pairs) each
    const int sc = sg * 8;
    const int prow0 = pg * 8;

    // W tile -> SMEM, once per block
    for (int idx = tid; idx < TP*TS/4; idx += 192) {
        int row = idx / (TS/4), col = idx % (TS/4);
        float4 v = *reinterpret_cast<const float4*>(&W[(size_t)(p0+row)*SEQ + s0 + col*4]);
        *reinterpret_cast<float4*>(&sW[row*TS + col*4]) = v;
    }

    // prologue: batch b_beg into buffer 0
    {
        const float* hb0 = g_h + (size_t)b_beg*ODIM;
        for (int idx = tid; idx < 16*TS/4; idx += 192) {
            int r = idx / (TS/4), col = idx % (TS/4);
            cp16(&sB[r*TS + col*4], &hb0[BOFF + r*SEQ + s0 + col*4]);
        }
        if (tid < TS/4) cp16(&sx[tid*4], &xg[(size_t)b_beg*SEQ + s0 + tid*4]);
        CP_COMMIT();
        #pragma unroll
        for (int k = 0; k < 4; ++k) {
            float a = hb0[p0*RNK + tid + k*192];
            sA[tid + k*192] = make_float2(a, a);
        }
        CP_WAIT0();
    }
    __syncthreads();

    for (int b = b_beg; b < b_end; ++b) {
        const int cur = (b - b_beg) & 1;
        const int nxt = cur ^ 1;
        const bool pf = (b + 1 < b_end);
        float apre[4];

        // issue prefetch for b+1
        if (pf) {
            const float* hbn = g_h + (size_t)(b+1)*ODIM;
            for (int idx = tid; idx < 16*TS/4; idx += 192) {
                int r = idx / (TS/4), col = idx % (TS/4);
                cp16(&sB[nxt*SB_F + r*TS + col*4], &hbn[BOFF + r*SEQ + s0 + col*4]);
            }
            if (tid < TS/4) cp16(&sx[nxt*TS + tid*4], &xg[(size_t)(b+1)*SEQ + s0 + tid*4]);
            CP_COMMIT();
            #pragma unroll
            for (int k = 0; k < 4; ++k) apre[k] = hbn[p0*RNK + tid + k*192];
        }

        if (active) {
            const float*  sBc = sB + cur*SB_F;
            const float2* sAc = sA + cur*SA_F;
            const float*  sxc = sx + cur*TS;

            unsigned long long acc[8][4];
            #pragma unroll
            for (int i = 0; i < 8; ++i) {
                const ulonglong2* wp =
                    reinterpret_cast<const ulonglong2*>(&sW[(prow0+i)*TS + sc]);
                acc[i][0] = wp[0].x; acc[i][1] = wp[0].y;
                acc[i][2] = wp[1].x; acc[i][3] = wp[1].y;
            }
            #pragma unroll
            for (int r = 0; r < RNK; ++r) {
                ulonglong2 bv0 = *reinterpret_cast<const ulonglong2*>(&sBc[r*TS + sc]);
                ulonglong2 bv1 = *reinterpret_cast<const ulonglong2*>(&sBc[r*TS + sc + 4]);
                #pragma unroll
                for (int i = 0; i < 8; ++i) {
                    unsigned long long ap =
                        *reinterpret_cast<const unsigned long long*>(&sAc[(prow0+i)*RNK + r]);
                    acc[i][0] = ffma2(ap, bv0.x, acc[i][0]);
                    acc[i][1] = ffma2(ap, bv0.y, acc[i][1]);
                    acc[i][2] = ffma2(ap, bv1.x, acc[i][2]);
                    acc[i][3] = ffma2(ap, bv1.y, acc[i][3]);
                }
            }
            // stores (streaming) + fused y dot
            ulonglong2 xp0 = *reinterpret_cast<const ulonglong2*>(&sxc[sc]);
            ulonglong2 xp1 = *reinterpret_cast<const ulonglong2*>(&sxc[sc + 4]);
            #pragma unroll
            for (int i = 0; i < 8; ++i) {
                size_t off = ((size_t)b*PRED + (p0 + prow0 + i))*SEQ + s0 + sc;
                __stcs(reinterpret_cast<float4*>(&weff[off]),     u2f4(acc[i][0], acc[i][1]));
                __stcs(reinterpret_cast<float4*>(&weff[off + 4]), u2f4(acc[i][2], acc[i][3]));
                unsigned long long y2 = 0ull;
                y2 = ffma2(acc[i][0], xp0.x, y2);
                y2 = ffma2(acc[i][1], xp0.y, y2);
                y2 = ffma2(acc[i][2], xp1.x, y2);
                y2 = ffma2(acc[i][3], xp1.y, y2);
                float lo, hi; unpack2(y2, lo, hi);
                atomicAdd(&yout[(size_t)b*PRED + p0 + prow0 + i], lo + hi);
            }
        }

        if (pf) {
            #pragma unroll
            for (int k = 0; k < 4; ++k)
                sA[nxt*SA_F + tid + k*192] = make_float2(apre[k], apre[k]);
            CP_WAIT0();
        }
        __syncthreads();
    }
}

// ---------------- launch ----------------
extern "C" void kernel_launch(void* const* d_in, const int* in_sizes, int n_in,
                              void* d_out, int out_size) {
    const float* x   = (const float*)d_in[0];  // (256,720,1)
    const float* ctx = (const float*)d_in[1];  // (256,128)
    const float* W   = (const float*)d_in[2];  // (720,720)
    const float* W1  = (const float*)d_in[3];  // (64,128)
    const float* b1  = (const float*)d_in[4];  // (64,)
    const float* W2  = (const float*)d_in[5];  // (23040,64)
    const float* b2  = (const float*)d_in[6];  // (23040,)
    float* out  = (float*)d_out;
    float* y    = out;            // first YSZ elements
    float* weff = out + YSZ;      // then W_eff

    hidden_kernel<<<NB, 128>>>(ctx, W1, b1);
    mlp2_kernel<<<dim3(ODIM/64, NB/64), dim3(16,16)>>>(W2, b2);
    zy_kernel<<<YSZ/(4*256), 256>>>(y);

    cudaFuncSetAttribute(weff_kernel, cudaFuncAttributeMaxDynamicSharedMemorySize, WEFF_SMEM);
    weff_kernel<<<dim3(PRED/TP, SEQ/TS, 6), 192, WEFF_SMEM>>>(W, x, weff, y);
}

// round 5
// speedup vs baseline: 1.5329x; 1.5329x over previous
#include <cuda_runtime.h>
#include <cstdint>

// Problem constants
#define NB   256
#define SEQ  720
#define PRED 720
#define RNK  16
#define CTXD 128
#define HIDD 64
#define ODIM (RNK*(SEQ+PRED))   // 23040
#define BOFF (RNK*PRED)         // 11520, B_delta at h[b][11520 + r*720 + s]
#define YSZ  (NB*PRED)          // 184320

// Scratch (device globals: allocation-free)
__device__ __align__(128) float g_hidden[NB*HIDD];
__device__ __align__(128) float g_h[(size_t)NB*ODIM];   // hyper-MLP output, 23.6 MB

// ---------------- packed f32x2 + async-copy helpers ----------------
__device__ __forceinline__ unsigned long long ffma2(unsigned long long a,
                                                    unsigned long long b,
                                                    unsigned long long c) {
    unsigned long long d;
    asm("fma.rn.f32x2 %0, %1, %2, %3;" : "=l"(d) : "l"(a), "l"(b), "l"(c));
    return d;
}
__device__ __forceinline__ unsigned long long dup2(float a) {
    unsigned long long d;
    asm("mov.b64 %0, {%1, %1};" : "=l"(d) : "f"(a));
    return d;
}
__device__ __forceinline__ float4 u2f4(unsigned long long a, unsigned long long b) {
    union { ulonglong2 u; float4 f; } c; c.u.x = a; c.u.y = b; return c.f;
}
__device__ __forceinline__ void unpack2(unsigned long long v, float& lo, float& hi) {
    asm("mov.b64 {%0, %1}, %2;" : "=f"(lo), "=f"(hi) : "l"(v));
}
__device__ __forceinline__ void cp16(void* smem_dst, const void* gmem_src) {
    unsigned s = (unsigned)__cvta_generic_to_shared(smem_dst);
    asm volatile("cp.async.cg.shared.global [%0], [%1], 16;" :: "r"(s), "l"(gmem_src));
}
#define CP_COMMIT() asm volatile("cp.async.commit_group;")
#define CP_WAIT0()  asm volatile("cp.async.wait_group 0;")

// ---------------- kernel 1a: hidden = relu(ctx @ W1^T + b1) ----------------
__global__ void hidden_kernel(const float* __restrict__ ctx,
                              const float* __restrict__ W1,
                              const float* __restrict__ b1) {
    __shared__ float sc[CTXD];
    int b = blockIdx.x;
    int t = threadIdx.x;               // 128 threads
    sc[t] = ctx[b*CTXD + t];
    __syncthreads();
    if (t < HIDD) {
        float s = b1[t];
        const float* w = W1 + t*CTXD;
        #pragma unroll 16
        for (int k = 0; k < CTXD; ++k) s += w[k]*sc[k];
        g_hidden[b*HIDD + t] = fmaxf(s, 0.f);
    }
}

// ---------------- kernel 1b: h = hidden @ W2^T + b2  (M=23040,N=256,K=64) ----
__global__ void __launch_bounds__(256) mlp2_kernel(const float* __restrict__ W2,
                                                   const float* __restrict__ b2) {
    __shared__ float sW2T[64*68];   // [k][o_local]
    __shared__ float sHT [64*68];   // [k][b_local]
    const int tx = threadIdx.x, ty = threadIdx.y;
    const int tid = ty*16 + tx;
    const int o0 = blockIdx.x*64, b0 = blockIdx.y*64;

    for (int idx = tid; idx < 4096; idx += 256) {
        int i = idx >> 6, k = idx & 63;
        sW2T[k*68 + i] = W2[(size_t)(o0+i)*HIDD + k];
        sHT [k*68 + i] = g_hidden[(b0+i)*HIDD + k];
    }
    __syncthreads();

    unsigned long long acc[4][2];
    #pragma unroll
    for (int j = 0; j < 4; ++j) { acc[j][0] = 0ull; acc[j][1] = 0ull; }

    #pragma unroll 16
    for (int k = 0; k < 64; ++k) {
        float4 hb = *reinterpret_cast<const float4*>(&sHT[k*68 + tx*4]);
        ulonglong2 w = *reinterpret_cast<const ulonglong2*>(&sW2T[k*68 + ty*4]);
        const float hv[4] = {hb.x, hb.y, hb.z, hb.w};
        #pragma unroll
        for (int j = 0; j < 4; ++j) {
            unsigned long long ap = dup2(hv[j]);
            acc[j][0] = ffma2(ap, w.x, acc[j][0]);
            acc[j][1] = ffma2(ap, w.y, acc[j][1]);
        }
    }
    float4 bias = *reinterpret_cast<const float4*>(&b2[o0 + ty*4]);
    #pragma unroll
    for (int j = 0; j < 4; ++j) {
        float4 v = u2f4(acc[j][0], acc[j][1]);
        v.x += bias.x; v.y += bias.y; v.z += bias.z; v.w += bias.w;
        *reinterpret_cast<float4*>(&g_h[(size_t)(b0 + tx*4 + j)*ODIM + o0 + ty*4]) = v;
    }
}

// ---------------- kernel 2: zero y ----------------
__global__ void zy_kernel(float* __restrict__ y) {
    int i = blockIdx.x*256 + threadIdx.x;     // grid 180, YSZ/4 = 46080 float4
    reinterpret_cast<float4*>(y)[i] = make_float4(0.f, 0.f, 0.f, 0.f);
}

// ---------------- kernel 3: W_eff = W + A@B, fused y = W_eff @ x ------------
// R3-proven shape: blockDim (64,4), thread tile 4p x 4s, pp loop over 3 groups
// of 16 p-rows (acc[4][2] scoped per group -> low register pressure).
// Double-buffered cp.async (B tile + x slice) + reg-prefetched A.
// y partials: 2 FFMA2 per row, 5-shuffle warp reduce (all threads converged;
// inactive lanes contribute 0), lane-0 RED.ADD.F32 into zero-init'd y.
#define TP 48
#define TS 240
#define SB_F (16*TS)                       // 3840 floats per B buffer
#define SA_F (TP*RNK)                      // 768 pairs per A buffer
#define WEFF_SMEM ((TP*TS + 2*SB_F + 2*TS)*4 + 2*SA_F*8)   // 91008 bytes

__global__ void __launch_bounds__(256, 2) weff_kernel(const float* __restrict__ W,
                                                      const float* __restrict__ xg,
                                                      float* __restrict__ weff,
                                                      float* __restrict__ yout) {
    extern __shared__ float smem[];
    float*  sW = smem;                                    // [TP][TS]
    float*  sB = smem + TP*TS;                            // [2][16][TS]
    float*  sx = smem + TP*TS + 2*SB_F;                   // [2][TS]
    float2* sA = reinterpret_cast<float2*>(smem + TP*TS + 2*SB_F + 2*TS); // [2][768]

    const int tx = threadIdx.x, ty = threadIdx.y;         // blockDim (64,4)
    const int tid = ty*64 + tx;
    const int p0 = blockIdx.x * TP;
    const int s0 = blockIdx.y * TS;
    const int b_beg = blockIdx.z * 43;
    const int b_end = min(NB, b_beg + 43);
    const bool active = (tx < TS/4);
    const int scol = active ? tx*4 : (TS - 4);            // clamped for idle lanes

    // W tile -> SMEM, once per block
    for (int idx = tid; idx < TP*TS/4; idx += 256) {
        int row = idx / (TS/4), col = idx % (TS/4);
        float4 v = *reinterpret_cast<const float4*>(&W[(size_t)(p0+row)*SEQ + s0 + col*4]);
        *reinterpret_cast<float4*>(&sW[row*TS + col*4]) = v;
    }

    // prologue: batch b_beg into buffer 0
    {
        const float* hb0 = g_h + (size_t)b_beg*ODIM;
        for (int idx = tid; idx < 16*TS/4; idx += 256) {
            int r = idx / (TS/4), col = idx % (TS/4);
            cp16(&sB[r*TS + col*4], &hb0[BOFF + r*SEQ + s0 + col*4]);
        }
        if (tid < TS/4) cp16(&sx[tid*4], &xg[(size_t)b_beg*SEQ + s0 + tid*4]);
        CP_COMMIT();
        #pragma unroll
        for (int k = 0; k < 3; ++k) {
            float a = hb0[p0*RNK + tid + k*256];
            sA[tid + k*256] = make_float2(a, a);
        }
        CP_WAIT0();
    }
    __syncthreads();

    for (int b = b_beg; b < b_end; ++b) {
        const int cur = (b - b_beg) & 1;
        const int nxt = cur ^ 1;
        const bool pf = (b + 1 < b_end);
        float apre[3];

        // issue prefetch for b+1 (cp.async B tile + x slice, LDG A into regs)
        if (pf) {
            const float* hbn = g_h + (size_t)(b+1)*ODIM;
            for (int idx = tid; idx < 16*TS/4; idx += 256) {
                int r = idx / (TS/4), col = idx % (TS/4);
                cp16(&sB[nxt*SB_F + r*TS + col*4], &hbn[BOFF + r*SEQ + s0 + col*4]);
            }
            if (tid < TS/4) cp16(&sx[nxt*TS + tid*4], &xg[(size_t)(b+1)*SEQ + s0 + tid*4]);
            CP_COMMIT();
            #pragma unroll
            for (int k = 0; k < 3; ++k) apre[k] = hbn[p0*RNK + tid + k*256];
        }

        // compute batch b from buffer cur (all 256 threads; stores guarded)
        {
            const float*  sBc = sB + cur*SB_F;
            const float2* sAc = sA + cur*SA_F;
            const ulonglong2 xp =
                *reinterpret_cast<const ulonglong2*>(&sx[cur*TS + scol]);

            #pragma unroll
            for (int pp = 0; pp < TP/16; ++pp) {
                const int prow = pp*16 + ty*4;
                unsigned long long acc[4][2];
                #pragma unroll
                for (int i = 0; i < 4; ++i) {
                    ulonglong2 w = *reinterpret_cast<const ulonglong2*>(&sW[(prow+i)*TS + scol]);
                    acc[i][0] = w.x; acc[i][1] = w.y;
                }
                #pragma unroll
                for (int r = 0; r < RNK; ++r) {
                    ulonglong2 bv = *reinterpret_cast<const ulonglong2*>(&sBc[r*TS + scol]);
                    #pragma unroll
                    for (int i = 0; i < 4; ++i) {
                        unsigned long long ap =
                            *reinterpret_cast<const unsigned long long*>(&sAc[(prow+i)*RNK + r]);
                        acc[i][0] = ffma2(ap, bv.x, acc[i][0]);
                        acc[i][1] = ffma2(ap, bv.y, acc[i][1]);
                    }
                }
                #pragma unroll
                for (int i = 0; i < 4; ++i) {
                    if (active) {
                        size_t off = ((size_t)b*PRED + (p0 + prow + i))*SEQ + s0 + scol;
                        __stcs(reinterpret_cast<float4*>(&weff[off]), u2f4(acc[i][0], acc[i][1]));
                    }
                    // fused y partial: W_eff row . x slice
                    unsigned long long y2 = ffma2(acc[i][0], xp.x, 0ull);
                    y2 = ffma2(acc[i][1], xp.y, y2);
                    float lo, hi; unpack2(y2, lo, hi);
                    float s = active ? (lo + hi) : 0.f;
                    #pragma unroll
                    for (int off = 16; off; off >>= 1)
                        s += __shfl_down_sync(0xffffffffu, s, off);
                    if ((tid & 31) == 0)
                        atomicAdd(&yout[(size_t)b*PRED + p0 + prow + i], s);
                }
            }
        }

        if (pf) {
            #pragma unroll
            for (int k = 0; k < 3; ++k)
                sA[nxt*SA_F + tid + k*256] = make_float2(apre[k], apre[k]);
            CP_WAIT0();
        }
        __syncthreads();
    }
}

// ---------------- launch ----------------
extern "C" void kernel_launch(void* const* d_in, const int* in_sizes, int n_in,
                              void* d_out, int out_size) {
    const float* x   = (const float*)d_in[0];  // (256,720,1)
    const float* ctx = (const float*)d_in[1];  // (256,128)
    const float* W   = (const float*)d_in[2];  // (720,720)
    const float* W1  = (const float*)d_in[3];  // (64,128)
    const float* b1  = (const float*)d_in[4];  // (64,)
    const float* W2  = (const float*)d_in[5];  // (23040,64)
    const float* b2  = (const float*)d_in[6];  // (23040,)
    float* out  = (float*)d_out;
    float* y    = out;            // first YSZ elements
    float* weff = out + YSZ;      // then W_eff

    hidden_kernel<<<NB, 128>>>(ctx, W1, b1);
    mlp2_kernel<<<dim3(ODIM/64, NB/64), dim3(16,16)>>>(W2, b2);
    zy_kernel<<<YSZ/(4*256), 256>>>(y);

    cudaFuncSetAttribute(weff_kernel, cudaFuncAttributeMaxDynamicSharedMemorySize, WEFF_SMEM);
    weff_kernel<<<dim3(PRED/TP, SEQ/TS, 6), dim3(64,4), WEFF_SMEM>>>(W, x, weff, y);
}

// round 6
// speedup vs baseline: 1.6182x; 1.0556x over previous
#include <cuda_runtime.h>
#include <cstdint>

// Problem constants
#define NB   256
#define SEQ  720
#define PRED 720
#define RNK  16
#define CTXD 128
#define HIDD 64
#define ODIM (RNK*(SEQ+PRED))   // 23040
#define BOFF (RNK*PRED)         // 11520, B_delta at h[b][11520 + r*720 + s]
#define YSZ  (NB*PRED)          // 184320

// Scratch (device globals: allocation-free)
__device__ __align__(128) float g_hidden[NB*HIDD];
__device__ __align__(128) float g_h[(size_t)NB*ODIM];   // hyper-MLP output, 23.6 MB
__device__ __align__(128) float g_t[NB*RNK];

// ---------------- packed f32x2 + async-copy helpers ----------------
__device__ __forceinline__ unsigned long long ffma2(unsigned long long a,
                                                    unsigned long long b,
                                                    unsigned long long c) {
    unsigned long long d;
    asm("fma.rn.f32x2 %0, %1, %2, %3;" : "=l"(d) : "l"(a), "l"(b), "l"(c));
    return d;
}
__device__ __forceinline__ unsigned long long dup2(float a) {
    unsigned long long d;
    asm("mov.b64 %0, {%1, %1};" : "=l"(d) : "f"(a));
    return d;
}
__device__ __forceinline__ float4 u2f4(unsigned long long a, unsigned long long b) {
    union { ulonglong2 u; float4 f; } c; c.u.x = a; c.u.y = b; return c.f;
}
__device__ __forceinline__ void unpack2(unsigned long long v, float& lo, float& hi) {
    asm("mov.b64 {%0, %1}, %2;" : "=f"(lo), "=f"(hi) : "l"(v));
}
__device__ __forceinline__ void cp16(void* smem_dst, const void* gmem_src) {
    unsigned s = (unsigned)__cvta_generic_to_shared(smem_dst);
    asm volatile("cp.async.cg.shared.global [%0], [%1], 16;" :: "r"(s), "l"(gmem_src));
}
#define CP_COMMIT() asm volatile("cp.async.commit_group;")
#define CP_WAIT0()  asm volatile("cp.async.wait_group 0;")

// ---------------- kernel 1a: hidden = relu(ctx @ W1^T + b1) ----------------
__global__ void hidden_kernel(const float* __restrict__ ctx,
                              const float* __restrict__ W1,
                              const float* __restrict__ b1) {
    __shared__ float sc[CTXD];
    int b = blockIdx.x;
    int t = threadIdx.x;               // 128 threads
    sc[t] = ctx[b*CTXD + t];
    __syncthreads();
    if (t < HIDD) {
        float s = b1[t];
        const float* w = W1 + t*CTXD;
        #pragma unroll 16
        for (int k = 0; k < CTXD; ++k) s += w[k]*sc[k];
        g_hidden[b*HIDD + t] = fmaxf(s, 0.f);
    }
}

// ---------------- kernel 1b: h = hidden @ W2^T + b2  (M=23040,N=256,K=64) ----
__global__ void __launch_bounds__(256) mlp2_kernel(const float* __restrict__ W2,
                                                   const float* __restrict__ b2) {
    __shared__ float sW2T[64*68];   // [k][o_local]
    __shared__ float sHT [64*68];   // [k][b_local]
    const int tx = threadIdx.x, ty = threadIdx.y;
    const int tid = ty*16 + tx;
    const int o0 = blockIdx.x*64, b0 = blockIdx.y*64;

    for (int idx = tid; idx < 4096; idx += 256) {
        int i = idx >> 6, k = idx & 63;
        sW2T[k*68 + i] = W2[(size_t)(o0+i)*HIDD + k];
        sHT [k*68 + i] = g_hidden[(b0+i)*HIDD + k];
    }
    __syncthreads();

    unsigned long long acc[4][2];
    #pragma unroll
    for (int j = 0; j < 4; ++j) { acc[j][0] = 0ull; acc[j][1] = 0ull; }

    #pragma unroll 16
    for (int k = 0; k < 64; ++k) {
        float4 hb = *reinterpret_cast<const float4*>(&sHT[k*68 + tx*4]);
        ulonglong2 w = *reinterpret_cast<const ulonglong2*>(&sW2T[k*68 + ty*4]);
        const float hv[4] = {hb.x, hb.y, hb.z, hb.w};
        #pragma unroll
        for (int j = 0; j < 4; ++j) {
            unsigned long long ap = dup2(hv[j]);
            acc[j][0] = ffma2(ap, w.x, acc[j][0]);
            acc[j][1] = ffma2(ap, w.y, acc[j][1]);
        }
    }
    float4 bias = *reinterpret_cast<const float4*>(&b2[o0 + ty*4]);
    #pragma unroll
    for (int j = 0; j < 4; ++j) {
        float4 v = u2f4(acc[j][0], acc[j][1]);
        v.x += bias.x; v.y += bias.y; v.z += bias.z; v.w += bias.w;
        *reinterpret_cast<float4*>(&g_h[(size_t)(b0 + tx*4 + j)*ODIM + o0 + ty*4]) = v;
    }
}

// ---------------- kernel 2: t[b][r] = B_delta[b,r,:] @ x[b,:] ----------------
__global__ void t_kernel(const float* __restrict__ x) {
    int b = blockIdx.x;
    int tid = threadIdx.x;            // 256 threads
    int r = tid >> 4, l = tid & 15;
    const float* bd = g_h + (size_t)b*ODIM + BOFF + r*SEQ;
    const float* xb = x + b*SEQ;
    float s = 0.f;
    for (int i = l; i < SEQ; i += 16) s += bd[i]*xb[i];
    #pragma unroll
    for (int off = 8; off; off >>= 1) s += __shfl_down_sync(0xffffffffu, s, off, 16);
    if (l == 0) g_t[b*RNK + r] = s;
}

// ---------------- kernel 3: y[b][p] = (W@x)[p,b] + A[b,p,:]·t[b,:] -----------
// 4 K-chunks of 180 (8 barriers total), f32x2 inner, conflict-free layouts.
#define YP  16
#define YB  64
#define YK  180
#define YKP 90            // k-pairs per chunk
#define YXST 65           // sX2 row stride in float2 (bank-conflict pad)
#define Y_SMEM (YKP*YXST*8 + YP*YKP*8 + YB*RNK*4)   // 62416 bytes

__global__ void __launch_bounds__(256) y_kernel(const float* __restrict__ W,
                                                const float* __restrict__ x,
                                                float* __restrict__ y) {
    extern __shared__ float ysm[];
    float2* sX2 = reinterpret_cast<float2*>(ysm);            // [kk][b] padded
    float2* sW2 = sX2 + YKP*YXST;                            // [p][kk]
    float*  st  = reinterpret_cast<float*>(sW2 + YP*YKP);    // [b][r]

    const int tx = threadIdx.x, ty = threadIdx.y;            // (64,4)
    const int tid = ty*64 + tx;
    const int p0 = blockIdx.x*YP, b0 = blockIdx.y*YB;

    for (int idx = tid; idx < YB*RNK; idx += 256) st[idx] = g_t[b0*RNK + idx];

    unsigned long long acc[4] = {0ull, 0ull, 0ull, 0ull};

    for (int c = 0; c < SEQ/YK; ++c) {
        const int k0 = c*YK;
        __syncthreads();
        for (int idx = tid; idx < YB*YKP; idx += 256) {
            int b = idx / YKP, kk = idx % YKP;
            sX2[kk*YXST + b] =
                *reinterpret_cast<const float2*>(&x[(size_t)(b0+b)*SEQ + k0 + kk*2]);
        }
        for (int idx = tid; idx < YP*YKP; idx += 256) {
            int p = idx / YKP, kk = idx % YKP;
            sW2[p*YKP + kk] =
                *reinterpret_cast<const float2*>(&W[(size_t)(p0+p)*SEQ + k0 + kk*2]);
        }
        __syncthreads();
        #pragma unroll 10
        for (int kk = 0; kk < YKP; ++kk) {
            unsigned long long xv =
                *reinterpret_cast<const unsigned long long*>(&sX2[kk*YXST + tx]);
            #pragma unroll
            for (int i = 0; i < 4; ++i) {
                unsigned long long wv =
                    *reinterpret_cast<const unsigned long long*>(&sW2[(ty*4+i)*YKP + kk]);
                acc[i] = ffma2(wv, xv, acc[i]);
            }
        }
    }
    // epilogue: + A[b,p,:] . t[b,:]
    {
        const int b = b0 + tx;
        const float* ga = g_h + (size_t)b*ODIM + (p0 + ty*4)*RNK;
        const float* tb = &st[tx*RNK];
        #pragma unroll
        for (int i = 0; i < 4; ++i) {
            float lo, hi; unpack2(acc[i], lo, hi);
            float d = 0.f;
            #pragma unroll
            for (int r = 0; r < RNK; ++r) d += ga[i*RNK + r]*tb[r];
            y[(size_t)b*PRED + p0 + ty*4 + i] = lo + hi + d;
        }
    }
}

// ---------------- kernel 4: W_eff = W + A_delta @ B_delta --------------------
// R3 structure; A pairs re-laid out [r][p] (stride 50, 16B aligned) so the 4
// per-row A loads become 2 LDS.128. Inner per r: 3 LDS.128 + 8 FFMA2.
#define TP 48
#define TS 240
#define SB_F (16*TS)                       // 3840 floats per B buffer
#define SA_ST 50                           // A row stride in float2
#define SA_F (RNK*SA_ST)                   // 800 float2 per A buffer
#define WEFF_SMEM ((TP*TS + 2*SB_F)*4 + 2*SA_F*8)   // 89600 bytes

__global__ void __launch_bounds__(256, 2) weff_kernel(const float* __restrict__ W,
                                                      float* __restrict__ weff) {
    extern __shared__ float smem[];
    float*  sW = smem;                                    // [TP][TS]
    float*  sB = smem + TP*TS;                            // [2][16][TS]
    float2* sA = reinterpret_cast<float2*>(smem + TP*TS + 2*SB_F); // [2][16][50]

    const int tx = threadIdx.x, ty = threadIdx.y;         // blockDim (64,4)
    const int tid = ty*64 + tx;
    const int p0 = blockIdx.x * TP;
    const int s0 = blockIdx.y * TS;
    const int b_beg = blockIdx.z * 43;
    const int b_end = min(NB, b_beg + 43);
    const bool active = (tx < TS/4);
    const int scol = tx*4;

    // W tile -> SMEM, once per block
    for (int idx = tid; idx < TP*TS/4; idx += 256) {
        int row = idx / (TS/4), col = idx % (TS/4);
        float4 v = *reinterpret_cast<const float4*>(&W[(size_t)(p0+row)*SEQ + s0 + col*4]);
        *reinterpret_cast<float4*>(&sW[row*TS + col*4]) = v;
    }

    // prologue: batch b_beg into buffer 0
    {
        const float* hb0 = g_h + (size_t)b_beg*ODIM;
        for (int idx = tid; idx < 16*TS/4; idx += 256) {
            int r = idx / (TS/4), col = idx % (TS/4);
            cp16(&sB[r*TS + col*4], &hb0[BOFF + r*SEQ + s0 + col*4]);
        }
        CP_COMMIT();
        #pragma unroll
        for (int k = 0; k < 3; ++k) {
            int idx = tid + k*256;
            int p = idx >> 4, r = idx & 15;
            float a = hb0[p0*RNK + idx];
            sA[r*SA_ST + p] = make_float2(a, a);
        }
        CP_WAIT0();
    }
    __syncthreads();

    for (int b = b_beg; b < b_end; ++b) {
        const int cur = (b - b_beg) & 1;
        const int nxt = cur ^ 1;
        const bool pf = (b + 1 < b_end);
        float apre[3];

        // issue prefetch for b+1
        if (pf) {
            const float* hbn = g_h + (size_t)(b+1)*ODIM;
            for (int idx = tid; idx < 16*TS/4; idx += 256) {
                int r = idx / (TS/4), col = idx % (TS/4);
                cp16(&sB[nxt*SB_F + r*TS + col*4], &hbn[BOFF + r*SEQ + s0 + col*4]);
            }
            CP_COMMIT();
            #pragma unroll
            for (int k = 0; k < 3; ++k) apre[k] = hbn[p0*RNK + tid + k*256];
        }

        if (active) {
            const float*  sBc = sB + cur*SB_F;
            const float2* sAc = sA + cur*SA_F;
            #pragma unroll
            for (int pp = 0; pp < TP/16; ++pp) {
                const int prow = pp*16 + ty*4;
                unsigned long long acc[4][2];
                #pragma unroll
                for (int i = 0; i < 4; ++i) {
                    ulonglong2 w = *reinterpret_cast<const ulonglong2*>(&sW[(prow+i)*TS + scol]);
                    acc[i][0] = w.x; acc[i][1] = w.y;
                }
                #pragma unroll
                for (int r = 0; r < RNK; ++r) {
                    ulonglong2 bv = *reinterpret_cast<const ulonglong2*>(&sBc[r*TS + scol]);
                    const float2* ap = &sAc[r*SA_ST + prow];
                    ulonglong2 a01 = *reinterpret_cast<const ulonglong2*>(ap);
                    ulonglong2 a23 = *reinterpret_cast<const ulonglong2*>(ap + 2);
                    acc[0][0] = ffma2(a01.x, bv.x, acc[0][0]);
                    acc[0][1] = ffma2(a01.x, bv.y, acc[0][1]);
                    acc[1][0] = ffma2(a01.y, bv.x, acc[1][0]);
                    acc[1][1] = ffma2(a01.y, bv.y, acc[1][1]);
                    acc[2][0] = ffma2(a23.x, bv.x, acc[2][0]);
                    acc[2][1] = ffma2(a23.x, bv.y, acc[2][1]);
                    acc[3][0] = ffma2(a23.y, bv.x, acc[3][0]);
                    acc[3][1] = ffma2(a23.y, bv.y, acc[3][1]);
                }
                #pragma unroll
                for (int i = 0; i < 4; ++i) {
                    size_t off = ((size_t)b*PRED + (p0 + prow + i))*SEQ + s0 + scol;
                    __stcs(reinterpret_cast<float4*>(&weff[off]), u2f4(acc[i][0], acc[i][1]));
                }
            }
        }

        if (pf) {
            #pragma unroll
            for (int k = 0; k < 3; ++k) {
                int idx = tid + k*256;
                int p = idx >> 4, r = idx & 15;
                sA[nxt*SA_F + r*SA_ST + p] = make_float2(apre[k], apre[k]);
            }
            CP_WAIT0();
        }
        __syncthreads();
    }
}

// ---------------- launch ----------------
extern "C" void kernel_launch(void* const* d_in, const int* in_sizes, int n_in,
                              void* d_out, int out_size) {
    const float* x   = (const float*)d_in[0];  // (256,720,1)
    const float* ctx = (const float*)d_in[1];  // (256,128)
    const float* W   = (const float*)d_in[2];  // (720,720)
    const float* W1  = (const float*)d_in[3];  // (64,128)
    const float* b1  = (const float*)d_in[4];  // (64,)
    const float* W2  = (const float*)d_in[5];  // (23040,64)
    const float* b2  = (const float*)d_in[6];  // (23040,)
    float* out  = (float*)d_out;
    float* y    = out;            // first YSZ elements
    float* weff = out + YSZ;      // then W_eff

    hidden_kernel<<<NB, 128>>>(ctx, W1, b1);
    mlp2_kernel<<<dim3(ODIM/64, NB/64), dim3(16,16)>>>(W2, b2);
    t_kernel<<<NB, 256>>>(x);

    cudaFuncSetAttribute(y_kernel, cudaFuncAttributeMaxDynamicSharedMemorySize, Y_SMEM);
    y_kernel<<<dim3(PRED/YP, NB/YB), dim3(64,4), Y_SMEM>>>(W, x, y);

    cudaFuncSetAttribute(weff_kernel, cudaFuncAttributeMaxDynamicSharedMemorySize, WEFF_SMEM);
    weff_kernel<<<dim3(PRED/TP, SEQ/TS, 6), dim3(64,4), WEFF_SMEM>>>(W, weff);
}

// round 7
// speedup vs baseline: 1.7994x; 1.1120x over previous
#include <cuda_runtime.h>
#include <cstdint>

// Problem constants
#define NB   256
#define SEQ  720
#define PRED 720
#define RNK  16
#define CTXD 128
#define HIDD 64
#define ODIM (RNK*(SEQ+PRED))   // 23040
#define BOFF (RNK*PRED)         // 11520, B_delta at h[b][11520 + r*720 + s]
#define YSZ  (NB*PRED)          // 184320

// Scratch (device globals: allocation-free)
__device__ __align__(128) float g_hidden[NB*HIDD];
__device__ __align__(128) float g_h[(size_t)NB*ODIM];   // hyper-MLP output, 23.6 MB
__device__ __align__(128) float g_t[NB*RNK];

// ---------------- packed f32x2 + async-copy helpers ----------------
__device__ __forceinline__ unsigned long long ffma2(unsigned long long a,
                                                    unsigned long long b,
                                                    unsigned long long c) {
    unsigned long long d;
    asm("fma.rn.f32x2 %0, %1, %2, %3;" : "=l"(d) : "l"(a), "l"(b), "l"(c));
    return d;
}
__device__ __forceinline__ unsigned long long dup2(float a) {
    unsigned long long d;
    asm("mov.b64 %0, {%1, %1};" : "=l"(d) : "f"(a));
    return d;
}
__device__ __forceinline__ float4 u2f4(unsigned long long a, unsigned long long b) {
    union { ulonglong2 u; float4 f; } c; c.u.x = a; c.u.y = b; return c.f;
}
__device__ __forceinline__ void unpack2(unsigned long long v, float& lo, float& hi) {
    asm("mov.b64 {%0, %1}, %2;" : "=f"(lo), "=f"(hi) : "l"(v));
}
__device__ __forceinline__ void cp16(void* smem_dst, const void* gmem_src) {
    unsigned s = (unsigned)__cvta_generic_to_shared(smem_dst);
    asm volatile("cp.async.cg.shared.global [%0], [%1], 16;" :: "r"(s), "l"(gmem_src));
}
#define CP_COMMIT() asm volatile("cp.async.commit_group;")
#define CP_WAIT0()  asm volatile("cp.async.wait_group 0;")

// ---------------- kernel 1a: hidden = relu(ctx @ W1^T + b1) ----------------
__global__ void hidden_kernel(const float* __restrict__ ctx,
                              const float* __restrict__ W1,
                              const float* __restrict__ b1) {
    __shared__ float sc[CTXD];
    int b = blockIdx.x;
    int t = threadIdx.x;               // 128 threads
    sc[t] = ctx[b*CTXD + t];
    __syncthreads();
    if (t < HIDD) {
        float s = b1[t];
        const float* w = W1 + t*CTXD;
        #pragma unroll 16
        for (int k = 0; k < CTXD; ++k) s += w[k]*sc[k];
        g_hidden[b*HIDD + t] = fmaxf(s, 0.f);
    }
}

// ---------------- kernel 1b: h = hidden @ W2^T + b2  (M=23040,N=256,K=64) ----
__global__ void __launch_bounds__(256) mlp2_kernel(const float* __restrict__ W2,
                                                   const float* __restrict__ b2) {
    __shared__ float sW2T[64*68];   // [k][o_local]
    __shared__ float sHT [64*68];   // [k][b_local]
    const int tx = threadIdx.x, ty = threadIdx.y;
    const int tid = ty*16 + tx;
    const int o0 = blockIdx.x*64, b0 = blockIdx.y*64;

    for (int idx = tid; idx < 4096; idx += 256) {
        int i = idx >> 6, k = idx & 63;
        sW2T[k*68 + i] = W2[(size_t)(o0+i)*HIDD + k];
        sHT [k*68 + i] = g_hidden[(b0+i)*HIDD + k];
    }
    __syncthreads();

    unsigned long long acc[4][2];
    #pragma unroll
    for (int j = 0; j < 4; ++j) { acc[j][0] = 0ull; acc[j][1] = 0ull; }

    #pragma unroll 16
    for (int k = 0; k < 64; ++k) {
        float4 hb = *reinterpret_cast<const float4*>(&sHT[k*68 + tx*4]);
        ulonglong2 w = *reinterpret_cast<const ulonglong2*>(&sW2T[k*68 + ty*4]);
        const float hv[4] = {hb.x, hb.y, hb.z, hb.w};
        #pragma unroll
        for (int j = 0; j < 4; ++j) {
            unsigned long long ap = dup2(hv[j]);
            acc[j][0] = ffma2(ap, w.x, acc[j][0]);
            acc[j][1] = ffma2(ap, w.y, acc[j][1]);
        }
    }
    float4 bias = *reinterpret_cast<const float4*>(&b2[o0 + ty*4]);
    #pragma unroll
    for (int j = 0; j < 4; ++j) {
        float4 v = u2f4(acc[j][0], acc[j][1]);
        v.x += bias.x; v.y += bias.y; v.z += bias.z; v.w += bias.w;
        *reinterpret_cast<float4*>(&g_h[(size_t)(b0 + tx*4 + j)*ODIM + o0 + ty*4]) = v;
    }
}

// ---------------- kernel 2: t[b][r] = B_delta[b,r,:] @ x[b,:] ----------------
__global__ void t_kernel(const float* __restrict__ x) {
    int b = blockIdx.x;
    int tid = threadIdx.x;            // 256 threads
    int r = tid >> 4, l = tid & 15;
    const float* bd = g_h + (size_t)b*ODIM + BOFF + r*SEQ;
    const float* xb = x + b*SEQ;
    float s = 0.f;
    for (int i = l; i < SEQ; i += 16) s += bd[i]*xb[i];
    #pragma unroll
    for (int off = 8; off; off >>= 1) s += __shfl_down_sync(0xffffffffu, s, off, 16);
    if (l == 0) g_t[b*RNK + r] = s;
}

// ---------------- kernel 3a: y init = A[b,p,:]·t[b,:] ------------------------
__global__ void yinit_kernel(float* __restrict__ y) {
    int idx = blockIdx.x*256 + threadIdx.x;   // grid 720
    int b = idx / PRED, p = idx - b*PRED;
    const float* a = g_h + (size_t)b*ODIM + p*RNK;
    const float* t = g_t + b*RNK;
    float s = 0.f;
    #pragma unroll
    for (int r = 0; r < RNK; ++r) s += a[r]*t[r];
    y[idx] = s;
}

// ---------------- kernel 3b: y += W@x, split-K with atomics ------------------
// grid (45, 4, 4): 720 blocks, each handles a 180-wide K chunk.
#define YP  16
#define YB  64
#define YKP 90            // k-pairs per chunk (180 k)
#define YXST 65           // sX2 row stride in float2
#define Y_SMEM (YKP*YXST*8 + YP*YKP*8)    // 58320 bytes

__global__ void __launch_bounds__(256) ysplit_kernel(const float* __restrict__ W,
                                                     const float* __restrict__ x,
                                                     float* __restrict__ y) {
    extern __shared__ float ysm[];
    float2* sX2 = reinterpret_cast<float2*>(ysm);            // [kk][b] padded
    float2* sW2 = sX2 + YKP*YXST;                            // [p][kk]

    const int tx = threadIdx.x, ty = threadIdx.y;            // (64,4)
    const int tid = ty*64 + tx;
    const int p0 = blockIdx.x*YP, b0 = blockIdx.y*YB;
    const int k0 = blockIdx.z*YKP*2;

    for (int idx = tid; idx < YB*YKP; idx += 256) {
        int b = idx / YKP, kk = idx - (idx/YKP)*YKP;
        sX2[kk*YXST + b] =
            *reinterpret_cast<const float2*>(&x[(size_t)(b0+b)*SEQ + k0 + kk*2]);
    }
    for (int idx = tid; idx < YP*YKP; idx += 256) {
        int p = idx / YKP, kk = idx - (idx/YKP)*YKP;
        sW2[p*YKP + kk] =
            *reinterpret_cast<const float2*>(&W[(size_t)(p0+p)*SEQ + k0 + kk*2]);
    }
    __syncthreads();

    unsigned long long acc[4] = {0ull, 0ull, 0ull, 0ull};
    #pragma unroll 10
    for (int kk = 0; kk < YKP; ++kk) {
        unsigned long long xv =
            *reinterpret_cast<const unsigned long long*>(&sX2[kk*YXST + tx]);
        #pragma unroll
        for (int i = 0; i < 4; ++i) {
            unsigned long long wv =
                *reinterpret_cast<const unsigned long long*>(&sW2[(ty*4+i)*YKP + kk]);
            acc[i] = ffma2(wv, xv, acc[i]);
        }
    }
    const int b = b0 + tx;
    #pragma unroll
    for (int i = 0; i < 4; ++i) {
        float lo, hi; unpack2(acc[i], lo, hi);
        atomicAdd(&y[(size_t)b*PRED + p0 + ty*4 + i], lo + hi);
    }
}

// ---------------- kernel 4: W_eff = W + A_delta @ B_delta --------------------
// r-loop hoisted over ALL 12 p-rows per thread: B tile read ONCE per r
// (crossbar traffic cut ~40%). acc = 24 u64 (48 regs), target <=128 total.
#define TP 48
#define TS 240
#define SB_F (16*TS)                       // 3840 floats per B buffer
#define SA_ST 50                           // A row stride in float2
#define SA_F (RNK*SA_ST)                   // 800 float2 per A buffer
#define WEFF_SMEM ((TP*TS + 2*SB_F)*4 + 2*SA_F*8)   // 89600 bytes

__global__ void __launch_bounds__(256, 2) weff_kernel(const float* __restrict__ W,
                                                      float* __restrict__ weff) {
    extern __shared__ float smem[];
    float*  sW = smem;                                    // [TP][TS]
    float*  sB = smem + TP*TS;                            // [2][16][TS]
    float2* sA = reinterpret_cast<float2*>(smem + TP*TS + 2*SB_F); // [2][16][50]

    const int tx = threadIdx.x, ty = threadIdx.y;         // blockDim (64,4)
    const int tid = ty*64 + tx;
    const int p0 = blockIdx.x * TP;
    const int s0 = blockIdx.y * TS;
    const int b_beg = blockIdx.z * 43;
    const int b_end = min(NB, b_beg + 43);
    const bool active = (tx < TS/4);
    const int scol = tx*4;

    // W tile -> SMEM, once per block
    for (int idx = tid; idx < TP*TS/4; idx += 256) {
        int row = idx / (TS/4), col = idx % (TS/4);
        float4 v = *reinterpret_cast<const float4*>(&W[(size_t)(p0+row)*SEQ + s0 + col*4]);
        *reinterpret_cast<float4*>(&sW[row*TS + col*4]) = v;
    }

    // prologue: batch b_beg into buffer 0
    {
        const float* hb0 = g_h + (size_t)b_beg*ODIM;
        for (int idx = tid; idx < 16*TS/4; idx += 256) {
            int r = idx / (TS/4), col = idx % (TS/4);
            cp16(&sB[r*TS + col*4], &hb0[BOFF + r*SEQ + s0 + col*4]);
        }
        CP_COMMIT();
        #pragma unroll
        for (int k = 0; k < 3; ++k) {
            int idx = tid + k*256;
            int p = idx >> 4, r = idx & 15;
            float a = hb0[p0*RNK + idx];
            sA[r*SA_ST + p] = make_float2(a, a);
        }
        CP_WAIT0();
    }
    __syncthreads();

    for (int b = b_beg; b < b_end; ++b) {
        const int cur = (b - b_beg) & 1;
        const int nxt = cur ^ 1;
        const bool pf = (b + 1 < b_end);
        float apre[3];

        // issue prefetch for b+1
        if (pf) {
            const float* hbn = g_h + (size_t)(b+1)*ODIM;
            for (int idx = tid; idx < 16*TS/4; idx += 256) {
                int r = idx / (TS/4), col = idx % (TS/4);
                cp16(&sB[nxt*SB_F + r*TS + col*4], &hbn[BOFF + r*SEQ + s0 + col*4]);
            }
            CP_COMMIT();
            #pragma unroll
            for (int k = 0; k < 3; ++k) apre[k] = hbn[p0*RNK + tid + k*256];
        }

        if (active) {
            const float*  sBc = sB + cur*SB_F;
            const float2* sAc = sA + cur*SA_F;

            unsigned long long acc[12][2];
            #pragma unroll
            for (int pp = 0; pp < 3; ++pp)
                #pragma unroll
                for (int i = 0; i < 4; ++i) {
                    ulonglong2 w = *reinterpret_cast<const ulonglong2*>(
                        &sW[(pp*16 + ty*4 + i)*TS + scol]);
                    acc[pp*4+i][0] = w.x; acc[pp*4+i][1] = w.y;
                }

            #pragma unroll
            for (int r = 0; r < RNK; ++r) {
                ulonglong2 bv = *reinterpret_cast<const ulonglong2*>(&sBc[r*TS + scol]);
                #pragma unroll
                for (int pp = 0; pp < 3; ++pp) {
                    const float2* ap = &sAc[r*SA_ST + pp*16 + ty*4];
                    ulonglong2 a01 = *reinterpret_cast<const ulonglong2*>(ap);
                    ulonglong2 a23 = *reinterpret_cast<const ulonglong2*>(ap + 2);
                    acc[pp*4+0][0] = ffma2(a01.x, bv.x, acc[pp*4+0][0]);
                    acc[pp*4+0][1] = ffma2(a01.x, bv.y, acc[pp*4+0][1]);
                    acc[pp*4+1][0] = ffma2(a01.y, bv.x, acc[pp*4+1][0]);
                    acc[pp*4+1][1] = ffma2(a01.y, bv.y, acc[pp*4+1][1]);
                    acc[pp*4+2][0] = ffma2(a23.x, bv.x, acc[pp*4+2][0]);
                    acc[pp*4+2][1] = ffma2(a23.x, bv.y, acc[pp*4+2][1]);
                    acc[pp*4+3][0] = ffma2(a23.y, bv.x, acc[pp*4+3][0]);
                    acc[pp*4+3][1] = ffma2(a23.y, bv.y, acc[pp*4+3][1]);
                }
            }

            #pragma unroll
            for (int pp = 0; pp < 3; ++pp)
                #pragma unroll
                for (int i = 0; i < 4; ++i) {
                    size_t off = ((size_t)b*PRED + (p0 + pp*16 + ty*4 + i))*SEQ + s0 + scol;
                    __stcs(reinterpret_cast<float4*>(&weff[off]),
                           u2f4(acc[pp*4+i][0], acc[pp*4+i][1]));
                }
        }

        if (pf) {
            #pragma unroll
            for (int k = 0; k < 3; ++k) {
                int idx = tid + k*256;
                int p = idx >> 4, r = idx & 15;
                sA[nxt*SA_F + r*SA_ST + p] = make_float2(apre[k], apre[k]);
            }
            CP_WAIT0();
        }
        __syncthreads();
    }
}

// ---------------- launch ----------------
extern "C" void kernel_launch(void* const* d_in, const int* in_sizes, int n_in,
                              void* d_out, int out_size) {
    const float* x   = (const float*)d_in[0];  // (256,720,1)
    const float* ctx = (const float*)d_in[1];  // (256,128)
    const float* W   = (const float*)d_in[2];  // (720,720)
    const float* W1  = (const float*)d_in[3];  // (64,128)
    const float* b1  = (const float*)d_in[4];  // (64,)
    const float* W2  = (const float*)d_in[5];  // (23040,64)
    const float* b2  = (const float*)d_in[6];  // (23040,)
    float* out  = (float*)d_out;
    float* y    = out;            // first YSZ elements
    float* weff = out + YSZ;      // then W_eff

    hidden_kernel<<<NB, 128>>>(ctx, W1, b1);
    mlp2_kernel<<<dim3(ODIM/64, NB/64), dim3(16,16)>>>(W2, b2);
    t_kernel<<<NB, 256>>>(x);
    yinit_kernel<<<YSZ/256, 256>>>(y);

    cudaFuncSetAttribute(ysplit_kernel, cudaFuncAttributeMaxDynamicSharedMemorySize, Y_SMEM);
    ysplit_kernel<<<dim3(PRED/YP, NB/YB, 4), dim3(64,4), Y_SMEM>>>(W, x, y);

    cudaFuncSetAttribute(weff_kernel, cudaFuncAttributeMaxDynamicSharedMemorySize, WEFF_SMEM);
    weff_kernel<<<dim3(PRED/TP, SEQ/TS, 6), dim3(64,4), WEFF_SMEM>>>(W, weff);
}

// round 8
// speedup vs baseline: 1.9809x; 1.1009x over previous
#include <cuda_runtime.h>
#include <cstdint>

// Problem constants
#define NB   256
#define SEQ  720
#define PRED 720
#define RNK  16
#define CTXD 128
#define HIDD 64
#define ODIM (RNK*(SEQ+PRED))   // 23040
#define BOFF (RNK*PRED)         // 11520, B_delta at h[b][11520 + r*720 + s]
#define YSZ  (NB*PRED)          // 184320

// Scratch (device globals: allocation-free)
__device__ __align__(128) float g_hidden[NB*HIDD];
__device__ __align__(128) float g_h[(size_t)NB*ODIM];   // hyper-MLP output, 23.6 MB
__device__ __align__(128) float g_t[NB*RNK];

// ---------------- packed f32x2 + async-copy helpers ----------------
__device__ __forceinline__ unsigned long long ffma2(unsigned long long a,
                                                    unsigned long long b,
                                                    unsigned long long c) {
    unsigned long long d;
    asm("fma.rn.f32x2 %0, %1, %2, %3;" : "=l"(d) : "l"(a), "l"(b), "l"(c));
    return d;
}
__device__ __forceinline__ unsigned long long dup2(float a) {
    unsigned long long d;
    asm("mov.b64 %0, {%1, %1};" : "=l"(d) : "f"(a));
    return d;
}
__device__ __forceinline__ float4 u2f4(unsigned long long a, unsigned long long b) {
    union { ulonglong2 u; float4 f; } c; c.u.x = a; c.u.y = b; return c.f;
}
__device__ __forceinline__ void unpack2(unsigned long long v, float& lo, float& hi) {
    asm("mov.b64 {%0, %1}, %2;" : "=f"(lo), "=f"(hi) : "l"(v));
}
__device__ __forceinline__ void cp16(void* smem_dst, const void* gmem_src) {
    unsigned s = (unsigned)__cvta_generic_to_shared(smem_dst);
    asm volatile("cp.async.cg.shared.global [%0], [%1], 16;" :: "r"(s), "l"(gmem_src));
}
#define CP_COMMIT() asm volatile("cp.async.commit_group;")
#define CP_WAIT0()  asm volatile("cp.async.wait_group 0;")

// ---------------- kernel 1a: hidden = relu(ctx @ W1^T + b1) ----------------
__global__ void hidden_kernel(const float* __restrict__ ctx,
                              const float* __restrict__ W1,
                              const float* __restrict__ b1) {
    __shared__ float sc[CTXD];
    int b = blockIdx.x;
    int t = threadIdx.x;               // 128 threads
    sc[t] = ctx[b*CTXD + t];
    __syncthreads();
    if (t < HIDD) {
        float s = b1[t];
        const float* w = W1 + t*CTXD;
        #pragma unroll 16
        for (int k = 0; k < CTXD; ++k) s += w[k]*sc[k];
        g_hidden[b*HIDD + t] = fmaxf(s, 0.f);
    }
}

// ---------------- kernel 1b: h = hidden @ W2^T + b2  (M=23040,N=256,K=64) ----
__global__ void __launch_bounds__(256) mlp2_kernel(const float* __restrict__ W2,
                                                   const float* __restrict__ b2) {
    __shared__ float sW2T[64*68];   // [k][o_local]
    __shared__ float sHT [64*68];   // [k][b_local]
    const int tx = threadIdx.x, ty = threadIdx.y;
    const int tid = ty*16 + tx;
    const int o0 = blockIdx.x*64, b0 = blockIdx.y*64;

    for (int idx = tid; idx < 4096; idx += 256) {
        int i = idx >> 6, k = idx & 63;
        sW2T[k*68 + i] = W2[(size_t)(o0+i)*HIDD + k];
        sHT [k*68 + i] = g_hidden[(b0+i)*HIDD + k];
    }
    __syncthreads();

    unsigned long long acc[4][2];
    #pragma unroll
    for (int j = 0; j < 4; ++j) { acc[j][0] = 0ull; acc[j][1] = 0ull; }

    #pragma unroll 16
    for (int k = 0; k < 64; ++k) {
        float4 hb = *reinterpret_cast<const float4*>(&sHT[k*68 + tx*4]);
        ulonglong2 w = *reinterpret_cast<const ulonglong2*>(&sW2T[k*68 + ty*4]);
        const float hv[4] = {hb.x, hb.y, hb.z, hb.w};
        #pragma unroll
        for (int j = 0; j < 4; ++j) {
            unsigned long long ap = dup2(hv[j]);
            acc[j][0] = ffma2(ap, w.x, acc[j][0]);
            acc[j][1] = ffma2(ap, w.y, acc[j][1]);
        }
    }
    float4 bias = *reinterpret_cast<const float4*>(&b2[o0 + ty*4]);
    #pragma unroll
    for (int j = 0; j < 4; ++j) {
        float4 v = u2f4(acc[j][0], acc[j][1]);
        v.x += bias.x; v.y += bias.y; v.z += bias.z; v.w += bias.w;
        *reinterpret_cast<float4*>(&g_h[(size_t)(b0 + tx*4 + j)*ODIM + o0 + ty*4]) = v;
    }
}

// ---------------- kernel 2: t[b][r] = B_delta[b,r,:] @ x[b,:] ----------------
__global__ void t_kernel(const float* __restrict__ x) {
    int b = blockIdx.x;
    int tid = threadIdx.x;            // 256 threads
    int r = tid >> 4, l = tid & 15;
    const float* bd = g_h + (size_t)b*ODIM + BOFF + r*SEQ;
    const float* xb = x + b*SEQ;
    float s = 0.f;
    for (int i = l; i < SEQ; i += 16) s += bd[i]*xb[i];
    #pragma unroll
    for (int off = 8; off; off >>= 1) s += __shfl_down_sync(0xffffffffu, s, off, 16);
    if (l == 0) g_t[b*RNK + r] = s;
}

// ---------------- kernel 3a: y init = A[b,p,:]·t[b,:] ------------------------
__global__ void yinit_kernel(float* __restrict__ y) {
    int idx = blockIdx.x*256 + threadIdx.x;   // grid 720
    int b = idx / PRED, p = idx - b*PRED;
    const float* a = g_h + (size_t)b*ODIM + p*RNK;
    const float* t = g_t + b*RNK;
    float s = 0.f;
    #pragma unroll
    for (int r = 0; r < RNK; ++r) s += a[r]*t[r];
    y[idx] = s;
}

// ---------------- kernel 3b: y += W@x, split-K with atomics ------------------
#define YP  16
#define YB  64
#define YKP 90            // k-pairs per chunk (180 k)
#define YXST 65           // sX2 row stride in float2
#define Y_SMEM (YKP*YXST*8 + YP*YKP*8)    // 58320 bytes

__global__ void __launch_bounds__(256) ysplit_kernel(const float* __restrict__ W,
                                                     const float* __restrict__ x,
                                                     float* __restrict__ y) {
    extern __shared__ float ysm[];
    float2* sX2 = reinterpret_cast<float2*>(ysm);            // [kk][b] padded
    float2* sW2 = sX2 + YKP*YXST;                            // [p][kk]

    const int tx = threadIdx.x, ty = threadIdx.y;            // (64,4)
    const int tid = ty*64 + tx;
    const int p0 = blockIdx.x*YP, b0 = blockIdx.y*YB;
    const int k0 = blockIdx.z*YKP*2;

    for (int idx = tid; idx < YB*YKP; idx += 256) {
        int b = idx / YKP, kk = idx - (idx/YKP)*YKP;
        sX2[kk*YXST + b] =
            *reinterpret_cast<const float2*>(&x[(size_t)(b0+b)*SEQ + k0 + kk*2]);
    }
    for (int idx = tid; idx < YP*YKP; idx += 256) {
        int p = idx / YKP, kk = idx - (idx/YKP)*YKP;
        sW2[p*YKP + kk] =
            *reinterpret_cast<const float2*>(&W[(size_t)(p0+p)*SEQ + k0 + kk*2]);
    }
    __syncthreads();

    unsigned long long acc[4] = {0ull, 0ull, 0ull, 0ull};
    #pragma unroll 10
    for (int kk = 0; kk < YKP; ++kk) {
        unsigned long long xv =
            *reinterpret_cast<const unsigned long long*>(&sX2[kk*YXST + tx]);
        #pragma unroll
        for (int i = 0; i < 4; ++i) {
            unsigned long long wv =
                *reinterpret_cast<const unsigned long long*>(&sW2[(ty*4+i)*YKP + kk]);
            acc[i] = ffma2(wv, xv, acc[i]);
        }
    }
    const int b = b0 + tx;
    #pragma unroll
    for (int i = 0; i < 4; ++i) {
        float lo, hi; unpack2(acc[i], lo, hi);
        atomicAdd(&y[(size_t)b*PRED + p0 + ty*4 + i], lo + hi);
    }
}

// ---------------- kernel 4: W_eff = W + A_delta @ B_delta --------------------
// L1TEX-wavefront-minimized: B hoisted (1 LDS.128/r), A stored as PLAIN floats
// (1 broadcast LDS.128 per 4 rows per r, dup2 in registers), W read once,
// streaming stores. ~208 wf/warp/batch. acc 24 u64 but fewer temps than R7.
#define TP 48
#define TS 240
#define SB_F (16*TS)                       // 3840 floats per B buffer
#define SA_ST 52                           // A row stride in floats (pad)
#define SA_F (RNK*SA_ST)                   // 832 floats per A buffer
#define WEFF_SMEM ((TP*TS + 2*SB_F + 2*SA_F)*4)   // 83456 bytes

__global__ void __launch_bounds__(256, 2) weff_kernel(const float* __restrict__ W,
                                                      float* __restrict__ weff) {
    extern __shared__ float smem[];
    float* sW = smem;                                 // [TP][TS]
    float* sB = smem + TP*TS;                         // [2][16][TS]
    float* sA = smem + TP*TS + 2*SB_F;                // [2][16][SA_ST] plain

    const int tx = threadIdx.x, ty = threadIdx.y;     // blockDim (64,4)
    const int tid = ty*64 + tx;
    const int p0 = blockIdx.x * TP;
    const int s0 = blockIdx.y * TS;
    const int b_beg = blockIdx.z * 43;
    const int b_end = min(NB, b_beg + 43);
    const bool active = (tx < TS/4);
    const int scol = tx*4;

    // W tile -> SMEM, once per block
    for (int idx = tid; idx < TP*TS/4; idx += 256) {
        int row = idx / (TS/4), col = idx % (TS/4);
        float4 v = *reinterpret_cast<const float4*>(&W[(size_t)(p0+row)*SEQ + s0 + col*4]);
        *reinterpret_cast<float4*>(&sW[row*TS + col*4]) = v;
    }

    // prologue: batch b_beg into buffer 0
    {
        const float* hb0 = g_h + (size_t)b_beg*ODIM;
        for (int idx = tid; idx < 16*TS/4; idx += 256) {
            int r = idx / (TS/4), col = idx % (TS/4);
            cp16(&sB[r*TS + col*4], &hb0[BOFF + r*SEQ + s0 + col*4]);
        }
        CP_COMMIT();
        #pragma unroll
        for (int k = 0; k < 3; ++k) {
            int idx = tid + k*256;
            int p = idx >> 4, r = idx & 15;
            sA[r*SA_ST + p] = hb0[p0*RNK + idx];
        }
        CP_WAIT0();
    }
    __syncthreads();

    for (int b = b_beg; b < b_end; ++b) {
        const int cur = (b - b_beg) & 1;
        const int nxt = cur ^ 1;
        const bool pf = (b + 1 < b_end);
        float apre[3];

        // issue prefetch for b+1
        if (pf) {
            const float* hbn = g_h + (size_t)(b+1)*ODIM;
            for (int idx = tid; idx < 16*TS/4; idx += 256) {
                int r = idx / (TS/4), col = idx % (TS/4);
                cp16(&sB[nxt*SB_F + r*TS + col*4], &hbn[BOFF + r*SEQ + s0 + col*4]);
            }
            CP_COMMIT();
            #pragma unroll
            for (int k = 0; k < 3; ++k) apre[k] = hbn[p0*RNK + tid + k*256];
        }

        if (active) {
            const float* sBc = sB + cur*SB_F;
            const float* sAc = sA + cur*SA_F;

            unsigned long long acc[12][2];
            #pragma unroll
            for (int pp = 0; pp < 3; ++pp)
                #pragma unroll
                for (int i = 0; i < 4; ++i) {
                    ulonglong2 w = *reinterpret_cast<const ulonglong2*>(
                        &sW[(pp*16 + ty*4 + i)*TS + scol]);
                    acc[pp*4+i][0] = w.x; acc[pp*4+i][1] = w.y;
                }

            #pragma unroll
            for (int r = 0; r < RNK; ++r) {
                ulonglong2 bv = *reinterpret_cast<const ulonglong2*>(&sBc[r*TS + scol]);
                #pragma unroll
                for (int pp = 0; pp < 3; ++pp) {
                    // one broadcast LDS.128 covers 4 rows' A values
                    float4 av = *reinterpret_cast<const float4*>(
                        &sAc[r*SA_ST + pp*16 + ty*4]);
                    unsigned long long a0 = dup2(av.x), a1 = dup2(av.y);
                    unsigned long long a2 = dup2(av.z), a3 = dup2(av.w);
                    acc[pp*4+0][0] = ffma2(a0, bv.x, acc[pp*4+0][0]);
                    acc[pp*4+0][1] = ffma2(a0, bv.y, acc[pp*4+0][1]);
                    acc[pp*4+1][0] = ffma2(a1, bv.x, acc[pp*4+1][0]);
                    acc[pp*4+1][1] = ffma2(a1, bv.y, acc[pp*4+1][1]);
                    acc[pp*4+2][0] = ffma2(a2, bv.x, acc[pp*4+2][0]);
                    acc[pp*4+2][1] = ffma2(a2, bv.y, acc[pp*4+2][1]);
                    acc[pp*4+3][0] = ffma2(a3, bv.x, acc[pp*4+3][0]);
                    acc[pp*4+3][1] = ffma2(a3, bv.y, acc[pp*4+3][1]);
                }
            }

            #pragma unroll
            for (int pp = 0; pp < 3; ++pp)
                #pragma unroll
                for (int i = 0; i < 4; ++i) {
                    size_t off = ((size_t)b*PRED + (p0 + pp*16 + ty*4 + i))*SEQ + s0 + scol;
                    __stcs(reinterpret_cast<float4*>(&weff[off]),
                           u2f4(acc[pp*4+i][0], acc[pp*4+i][1]));
                }
        }

        if (pf) {
            #pragma unroll
            for (int k = 0; k < 3; ++k) {
                int idx = tid + k*256;
                int p = idx >> 4, r = idx & 15;
                sA[nxt*SA_F + r*SA_ST + p] = apre[k];
            }
            CP_WAIT0();
        }
        __syncthreads();
    }
}

// ---------------- launch ----------------
extern "C" void kernel_launch(void* const* d_in, const int* in_sizes, int n_in,
                              void* d_out, int out_size) {
    const float* x   = (const float*)d_in[0];  // (256,720,1)
    const float* ctx = (const float*)d_in[1];  // (256,128)
    const float* W   = (const float*)d_in[2];  // (720,720)
    const float* W1  = (const float*)d_in[3];  // (64,128)
    const float* b1  = (const float*)d_in[4];  // (64,)
    const float* W2  = (const float*)d_in[5];  // (23040,64)
    const float* b2  = (const float*)d_in[6];  // (23040,)
    float* out  = (float*)d_out;
    float* y    = out;            // first YSZ elements
    float* weff = out + YSZ;      // then W_eff

    hidden_kernel<<<NB, 128>>>(ctx, W1, b1);
    mlp2_kernel<<<dim3(ODIM/64, NB/64), dim3(16,16)>>>(W2, b2);
    t_kernel<<<NB, 256>>>(x);
    yinit_kernel<<<YSZ/256, 256>>>(y);

    cudaFuncSetAttribute(ysplit_kernel, cudaFuncAttributeMaxDynamicSharedMemorySize, Y_SMEM);
    ysplit_kernel<<<dim3(PRED/YP, NB/YB, 4), dim3(64,4), Y_SMEM>>>(W, x, y);

    cudaFuncSetAttribute(weff_kernel, cudaFuncAttributeMaxDynamicSharedMemorySize, WEFF_SMEM);
    weff_kernel<<<dim3(PRED/TP, SEQ/TS, 6), dim3(64,4), WEFF_SMEM>>>(W, weff);
}